// round 4
// baseline (speedup 1.0000x reference)
#include <cuda_runtime.h>
#include <cuda_fp16.h>

// Bilateral filter: B=8, C=3, H=W=512, K=5, sigma_s=2.0, sigma_r=0.1
//
// R4: halve MUFU pressure with ex2.approx.f16x2 — one MUFU op computes the
// exp for BOTH pixels owned by a thread (2 vertically adjacent pixels share
// each tap's spatial term). Center tap needs no exp (w = spatial center).
// Args are computed in fp32, packed to half2 only for the EX2.
//
// w = exp2( log2(spatial) - ((n-c)*C1)^2 ),  C1 = sqrt(50*log2(e))

#define HW 512
#define TILE 32
#define PAD 2
#define SMW (TILE + 2*PAD)   // 36
#define SMH (TILE + 2*PAD)   // 36

__device__ __forceinline__ __half2 h2exp2_asm(__half2 v) {
    __half2 r;
    asm("ex2.approx.f16x2 %0, %1;"
        : "=r"(*reinterpret_cast<unsigned*>(&r))
        : "r"(*reinterpret_cast<const unsigned*>(&v)));
    return r;
}

__device__ __forceinline__ int reflect512(int g) {
    g = (g < 0) ? -g : g;
    return (g > 511) ? (1022 - g) : g;
}

__global__ __launch_bounds__(512, 3)
void bilateral_kernel(const float* __restrict__ x,
                      const float* __restrict__ spatial,
                      float* __restrict__ out) {
    __shared__ float tile[SMH][SMW];
    __shared__ float ls[25];
    __shared__ float scen;

    const int bx = blockIdx.x * TILE;
    const int by = blockIdx.y * TILE;
    const float* __restrict__ src = x   + (size_t)blockIdx.z * (HW * HW);
    float* __restrict__       dst = out + (size_t)blockIdx.z * (HW * HW);

    const int tid = threadIdx.y * 32 + threadIdx.x;

    if (tid < 25) ls[tid] = __log2f(spatial[tid]);
    if (tid == 25) scen = spatial[12];   // center weight: exp(0)*spatial = spatial

    // Cooperative tile load with reflect padding (36x36, 512 threads)
    #pragma unroll
    for (int idx = tid; idx < SMH * SMW; idx += 512) {
        int ly = idx / SMW;
        int lx = idx - ly * SMW;
        tile[ly][lx] = src[reflect512(by + ly - PAD) * HW +
                           reflect512(bx + lx - PAD)];
    }
    __syncthreads();

    const float C1 = 8.4932165750422091f;  // sqrt(50 * log2(e))

    const int lx  = threadIdx.x;        // 0..31
    const int ly0 = threadIdx.y * 2;    // 2 output rows per thread
    const float sc = scen;

    float c0 = tile[ly0 + PAD + 0][lx + PAD];
    float c1 = tile[ly0 + PAD + 1][lx + PAD];
    float cC10 = c0 * C1;
    float cC11 = c1 * C1;
    float wsum0 = 0.0f, wsum1 = 0.0f, acc0 = 0.0f, acc1 = 0.0f;

    #pragma unroll
    for (int j = 0; j < 5; j++) {
        // one 6-tall register column serves both pixels' 5-tall windows
        float v[6];
        #pragma unroll
        for (int r = 0; r < 6; r++) {
            v[r] = tile[ly0 + r][lx + j];
        }
        #pragma unroll
        for (int i = 0; i < 5; i++) {
            const float n0 = v[i];
            const float n1 = v[i + 1];
            if (i == 2 && j == 2) {
                // center tap: weight is exactly the spatial center, no exp
                wsum0 += sc;  acc0 = fmaf(sc, n0, acc0);
                wsum1 += sc;  acc1 = fmaf(sc, n1, acc1);
            } else {
                const float lsij = ls[i * 5 + j];
                float d0 = fmaf(n0, C1, -cC10);            // FFMA-imm
                float d1 = fmaf(n1, C1, -cC11);
                float g0 = fmaf(d0, -d0, lsij);
                float g1 = fmaf(d1, -d1, lsij);
                __half2 w2 = h2exp2_asm(__floats2half2_rn(g0, g1));
                float w0 = __low2float(w2);
                float w1 = __high2float(w2);
                wsum0 += w0;  acc0 = fmaf(w0, n0, acc0);
                wsum1 += w1;  acc1 = fmaf(w1, n1, acc1);
            }
        }
    }

    const int gx = bx + lx;
    dst[(by + ly0 + 0) * HW + gx] = __fdividef(acc0, wsum0);
    dst[(by + ly0 + 1) * HW + gx] = __fdividef(acc1, wsum1);
}

extern "C" void kernel_launch(void* const* d_in, const int* in_sizes, int n_in,
                              void* d_out, int out_size) {
    const float* x       = (const float*)d_in[0];  // (8,3,512,512)
    const float* spatial = (const float*)d_in[1];  // (5,5)
    float* out           = (float*)d_out;

    dim3 block(32, 16);
    dim3 grid(HW / TILE, HW / TILE, 24);  // 16 x 16 x (B*C)
    bilateral_kernel<<<grid, block>>>(x, spatial, out);
}

// round 5
// speedup vs baseline: 1.4629x; 1.4629x over previous
#include <cuda_runtime.h>

// Bilateral filter: B=8, C=3, H=W=512, K=5, sigma_s=2.0, sigma_r=0.1
//
// R5: pairwise weight sharing (4x4 pixel patch per thread, 18.4 EX2/px) with
// the R3 overheads removed:
//   - log2(spatial) baked as immediates: spatial = exp(-d^2/8) exactly, so
//     ls(d^2) = -d^2 * log2(e)/8 and the center weight is exactly 1.0.
//   - tile values pre-scaled by C1 = sqrt(50*log2 e): pair weight is
//     w = exp2(fma(t,-t,ls)) with t = ya - yb (one FADD). Un-scale at the end.
//   - interior CTAs (36/64) skip reflect entirely, pow2 addressing.
//
// w(p,q) = spatial(d)*exp(-50 (xp-xq)^2) is symmetric -> one EX2 serves both
// owned endpoints. MUFU (EX2) lane throughput is the measured roofline.

#define HW   512
#define TILE 64
#define SROW 68
#define C1F  8.4932165750422091f
#define LSOF(dsq) (-0.18033688011112043f * (float)(dsq))   // log2(exp(-dsq/8))

__device__ __forceinline__ float ex2a(float v) {
    float y;
    asm("ex2.approx.ftz.f32 %0, %1;" : "=f"(y) : "f"(v));
    return y;
}

__device__ __forceinline__ int reflect512(int g) {
    g = (g < 0) ? -g : g;
    return (g > 511) ? (1022 - g) : g;
}

// ownership of a window-local coordinate (window is 8x8, owned core is 2..5)
#define OWN(rr,cc) ((rr) >= 2 && (rr) <= 5 && (cc) >= 2 && (cc) <= 5)

// one unordered pair; all index args compile-time constants after unrolling
#define PAIR(va, vb, ra, ca, rb, cb, di, dj) do {                              \
    const bool oa_ = OWN(ra, ca), ob_ = OWN(rb, cb);                           \
    if (oa_ || ob_) {                                                          \
        float t_ = (va) - (vb);                                                \
        float w_ = ex2a(fmaf(t_, -t_, LSOF((di)*(di)+(dj)*(dj))));             \
        if (oa_) { const int ia_ = ((ra)-2)*4 + ((ca)-2);                      \
                   wsum[ia_] += w_; acc[ia_] = fmaf(w_, (vb), acc[ia_]); }     \
        if (ob_) { const int ib_ = ((rb)-2)*4 + ((cb)-2);                      \
                   wsum[ib_] += w_; acc[ib_] = fmaf(w_, (va), acc[ib_]); }     \
    }                                                                          \
} while (0)

__global__ __launch_bounds__(256, 3)
void bilateral_kernel(const float* __restrict__ x,
                      float* __restrict__ out) {
    __shared__ float tile[68 * SROW];

    const int bx = blockIdx.x * TILE;
    const int by = blockIdx.y * TILE;
    const float* __restrict__ src = x   + (size_t)blockIdx.z * (HW * HW);
    float* __restrict__       dst = out + (size_t)blockIdx.z * (HW * HW);

    const int tx  = threadIdx.x;         // 0..15
    const int ty  = threadIdx.y;         // 0..15
    const int tid = ty * 16 + tx;

    const bool interior = (bx != 0) && (bx != HW - TILE) &&
                          (by != 0) && (by != HW - TILE);

    if (interior) {
        const float* base = src + (size_t)(by - 2) * HW + (bx - 2);
        const int c6 = tid & 63;
        const int r6 = tid >> 6;
        // main region: 68 rows x cols 0..63
        #pragma unroll
        for (int it = 0; it < 17; it++) {
            const int r = it * 4 + r6;
            tile[r * SROW + c6] = base[r * HW + c6] * C1F;
        }
        // strip: cols 64..67, 68 rows (272 elems, 2 guarded passes)
        #pragma unroll
        for (int it = 0; it < 2; it++) {
            const int idx = it * 256 + tid;
            if (idx < 272) {
                const int r = idx >> 2;
                const int c = 64 + (idx & 3);
                tile[r * SROW + c] = base[r * HW + c] * C1F;
            }
        }
    } else {
        for (int i = tid; i < 68 * 68; i += 256) {
            const int r = i / 68;
            const int c = i - r * 68;
            tile[r * SROW + c] = src[reflect512(by + r - 2) * HW +
                                     reflect512(bx + c - 2)] * C1F;
        }
    }
    __syncthreads();

    const int R0 = 4 * ty;   // smem row of window origin
    const int C0 = 4 * tx;   // smem col of window origin

    float wsum[16], acc[16];
    #pragma unroll
    for (int i = 0; i < 16; i++) { wsum[i] = 0.0f; acc[i] = 0.0f; }

    float rows[3][8];   // rolling 3-row window buffer (constant indices)

    #pragma unroll
    for (int r = 0; r < 8; r++) {
        const int cr = r % 3;

        // load window row r: cols C0..C0+7, two aligned float4
        {
            float4 a = *(const float4*)&tile[(R0 + r) * SROW + C0];
            float4 b = *(const float4*)&tile[(R0 + r) * SROW + C0 + 4];
            rows[cr][0] = a.x; rows[cr][1] = a.y;
            rows[cr][2] = a.z; rows[cr][3] = a.w;
            rows[cr][4] = b.x; rows[cr][5] = b.y;
            rows[cr][6] = b.z; rows[cr][7] = b.w;
        }

        // ---- center taps: weight is exactly 1.0, no exp
        if (r >= 2 && r <= 5) {
            #pragma unroll
            for (int c = 2; c <= 5; c++) {
                const int ia = (r - 2) * 4 + (c - 2);
                wsum[ia] += 1.0f;
                acc[ia]  += rows[cr][c];
            }
        }

        // ---- di=0 pairs (within row r)
        if (r >= 2 && r <= 5) {
            #pragma unroll
            for (int c = 1; c <= 5; c++)       // dj = 1
                PAIR(rows[cr][c], rows[cr][c+1], r, c, r, c+1, 0, 1);
            #pragma unroll
            for (int c = 0; c <= 5; c++)       // dj = 2
                PAIR(rows[cr][c], rows[cr][c+2], r, c, r, c+2, 0, 2);
        }

        // ---- di=1 pairs: rows (r-1, r)
        if (r >= 1) {
            const int pr = (r - 1) % 3;
            #pragma unroll
            for (int dj = -2; dj <= 2; dj++) {
                #pragma unroll
                for (int c = 0; c < 8; c++) {
                    const int cb = c + dj;
                    if (cb < 0 || cb > 7) continue;
                    PAIR(rows[pr][c], rows[cr][cb], r-1, c, r, cb, 1, dj);
                }
            }
        }

        // ---- di=2 pairs: rows (r-2, r)
        if (r >= 2) {
            const int p2 = (r - 2) % 3;
            #pragma unroll
            for (int dj = -2; dj <= 2; dj++) {
                #pragma unroll
                for (int c = 0; c < 8; c++) {
                    const int cb = c + dj;
                    if (cb < 0 || cb > 7) continue;
                    PAIR(rows[p2][c], rows[cr][cb], r-2, c, r, cb, 2, dj);
                }
            }
        }
    }

    // ---- normalize, un-scale by 1/C1, store
    const float INV = 1.0f / C1F;
    #pragma unroll
    for (int pr = 0; pr < 4; pr++) {
        float4 o;
        o.x = __fdividef(acc[pr*4 + 0], wsum[pr*4 + 0]) * INV;
        o.y = __fdividef(acc[pr*4 + 1], wsum[pr*4 + 1]) * INV;
        o.z = __fdividef(acc[pr*4 + 2], wsum[pr*4 + 2]) * INV;
        o.w = __fdividef(acc[pr*4 + 3], wsum[pr*4 + 3]) * INV;
        *(float4*)&dst[(by + R0 + pr) * HW + bx + C0] = o;
    }
}

extern "C" void kernel_launch(void* const* d_in, const int* in_sizes, int n_in,
                              void* d_out, int out_size) {
    const float* x = (const float*)d_in[0];  // (8,3,512,512)
    float* out     = (float*)d_out;

    dim3 block(16, 16);
    dim3 grid(HW / TILE, HW / TILE, 24);   // 8 x 8 x (B*C)
    bilateral_kernel<<<grid, block>>>(x, out);
}

// round 6
// speedup vs baseline: 1.4749x; 1.0082x over previous
#include <cuda_runtime.h>

// Bilateral filter: B=8, C=3, H=W=512, K=5, sigma_s=2.0, sigma_r=0.1
//
// R6: R5 (pairwise exp sharing, 18.4 EX2/px, baked log2-spatial immediates)
// + occupancy squeeze: __launch_bounds__(256,4) forces <=64 regs so 4 CTAs
// (32 warps) fit per SM instead of 3 (24). The kernel is latency-bound at
// issue=59%/MUFU=63%; more warp supply is the lever, floors unchanged.
//
// w(p,q) = spatial(d)*exp(-50 (xp-xq)^2) is symmetric -> one EX2 serves both
// owned endpoints. spatial = exp(-d^2/8) exactly, so log2-weights are
// compile-time constants and the center weight is exactly 1.0.

#define HW   512
#define TILE 64
#define SROW 68
#define C1F  8.4932165750422091f
#define LSOF(dsq) (-0.18033688011112043f * (float)(dsq))   // log2(exp(-dsq/8))

__device__ __forceinline__ float ex2a(float v) {
    float y;
    asm("ex2.approx.ftz.f32 %0, %1;" : "=f"(y) : "f"(v));
    return y;
}

__device__ __forceinline__ int reflect512(int g) {
    g = (g < 0) ? -g : g;
    return (g > 511) ? (1022 - g) : g;
}

// ownership of a window-local coordinate (window is 8x8, owned core is 2..5)
#define OWN(rr,cc) ((rr) >= 2 && (rr) <= 5 && (cc) >= 2 && (cc) <= 5)

// one unordered pair; all index args compile-time constants after unrolling
#define PAIR(va, vb, ra, ca, rb, cb, di, dj) do {                              \
    const bool oa_ = OWN(ra, ca), ob_ = OWN(rb, cb);                           \
    if (oa_ || ob_) {                                                          \
        float t_ = (va) - (vb);                                                \
        float w_ = ex2a(fmaf(t_, -t_, LSOF((di)*(di)+(dj)*(dj))));             \
        if (oa_) { const int ia_ = ((ra)-2)*4 + ((ca)-2);                      \
                   wsum[ia_] += w_; acc[ia_] = fmaf(w_, (vb), acc[ia_]); }     \
        if (ob_) { const int ib_ = ((rb)-2)*4 + ((cb)-2);                      \
                   wsum[ib_] += w_; acc[ib_] = fmaf(w_, (va), acc[ib_]); }     \
    }                                                                          \
} while (0)

__global__ __launch_bounds__(256, 4)
void bilateral_kernel(const float* __restrict__ x,
                      float* __restrict__ out) {
    __shared__ float tile[68 * SROW];

    const int bx = blockIdx.x * TILE;
    const int by = blockIdx.y * TILE;
    const float* __restrict__ src = x   + (size_t)blockIdx.z * (HW * HW);
    float* __restrict__       dst = out + (size_t)blockIdx.z * (HW * HW);

    const int tx  = threadIdx.x;         // 0..15
    const int ty  = threadIdx.y;         // 0..15
    const int tid = ty * 16 + tx;

    const bool interior = (bx != 0) && (bx != HW - TILE) &&
                          (by != 0) && (by != HW - TILE);

    if (interior) {
        const float* base = src + (size_t)(by - 2) * HW + (bx - 2);
        const int c6 = tid & 63;
        const int r6 = tid >> 6;
        // main region: 68 rows x cols 0..63
        #pragma unroll
        for (int it = 0; it < 17; it++) {
            const int r = it * 4 + r6;
            tile[r * SROW + c6] = base[r * HW + c6] * C1F;
        }
        // strip: cols 64..67, 68 rows (272 elems, 2 guarded passes)
        #pragma unroll
        for (int it = 0; it < 2; it++) {
            const int idx = it * 256 + tid;
            if (idx < 272) {
                const int r = idx >> 2;
                const int c = 64 + (idx & 3);
                tile[r * SROW + c] = base[r * HW + c] * C1F;
            }
        }
    } else {
        for (int i = tid; i < 68 * 68; i += 256) {
            const int r = i / 68;
            const int c = i - r * 68;
            tile[r * SROW + c] = src[reflect512(by + r - 2) * HW +
                                     reflect512(bx + c - 2)] * C1F;
        }
    }
    __syncthreads();

    const int R0 = 4 * ty;   // smem row of window origin
    const int C0 = 4 * tx;   // smem col of window origin

    float wsum[16], acc[16];
    #pragma unroll
    for (int i = 0; i < 16; i++) { wsum[i] = 0.0f; acc[i] = 0.0f; }

    float rows[3][8];   // rolling 3-row window buffer (constant indices)

    #pragma unroll
    for (int r = 0; r < 8; r++) {
        const int cr = r % 3;

        // load window row r: cols C0..C0+7, two aligned float4 (conflict-free)
        {
            float4 a = *(const float4*)&tile[(R0 + r) * SROW + C0];
            float4 b = *(const float4*)&tile[(R0 + r) * SROW + C0 + 4];
            rows[cr][0] = a.x; rows[cr][1] = a.y;
            rows[cr][2] = a.z; rows[cr][3] = a.w;
            rows[cr][4] = b.x; rows[cr][5] = b.y;
            rows[cr][6] = b.z; rows[cr][7] = b.w;
        }

        // ---- center taps: weight is exactly 1.0, no exp
        if (r >= 2 && r <= 5) {
            #pragma unroll
            for (int c = 2; c <= 5; c++) {
                const int ia = (r - 2) * 4 + (c - 2);
                wsum[ia] += 1.0f;
                acc[ia]  += rows[cr][c];
            }
        }

        // ---- di=0 pairs (within row r)
        if (r >= 2 && r <= 5) {
            #pragma unroll
            for (int c = 1; c <= 5; c++)       // dj = 1
                PAIR(rows[cr][c], rows[cr][c+1], r, c, r, c+1, 0, 1);
            #pragma unroll
            for (int c = 0; c <= 5; c++)       // dj = 2
                PAIR(rows[cr][c], rows[cr][c+2], r, c, r, c+2, 0, 2);
        }

        // ---- di=1 pairs: rows (r-1, r)
        if (r >= 1) {
            const int pr = (r - 1) % 3;
            #pragma unroll
            for (int dj = -2; dj <= 2; dj++) {
                #pragma unroll
                for (int c = 0; c < 8; c++) {
                    const int cb = c + dj;
                    if (cb < 0 || cb > 7) continue;
                    PAIR(rows[pr][c], rows[cr][cb], r-1, c, r, cb, 1, dj);
                }
            }
        }

        // ---- di=2 pairs: rows (r-2, r)
        if (r >= 2) {
            const int p2 = (r - 2) % 3;
            #pragma unroll
            for (int dj = -2; dj <= 2; dj++) {
                #pragma unroll
                for (int c = 0; c < 8; c++) {
                    const int cb = c + dj;
                    if (cb < 0 || cb > 7) continue;
                    PAIR(rows[p2][c], rows[cr][cb], r-2, c, r, cb, 2, dj);
                }
            }
        }
    }

    // ---- normalize, un-scale by 1/C1, store
    const float INV = 1.0f / C1F;
    #pragma unroll
    for (int pr = 0; pr < 4; pr++) {
        float4 o;
        o.x = __fdividef(acc[pr*4 + 0], wsum[pr*4 + 0]) * INV;
        o.y = __fdividef(acc[pr*4 + 1], wsum[pr*4 + 1]) * INV;
        o.z = __fdividef(acc[pr*4 + 2], wsum[pr*4 + 2]) * INV;
        o.w = __fdividef(acc[pr*4 + 3], wsum[pr*4 + 3]) * INV;
        *(float4*)&dst[(by + R0 + pr) * HW + bx + C0] = o;
    }
}

extern "C" void kernel_launch(void* const* d_in, const int* in_sizes, int n_in,
                              void* d_out, int out_size) {
    const float* x = (const float*)d_in[0];  // (8,3,512,512)
    float* out     = (float*)d_out;

    dim3 block(16, 16);
    dim3 grid(HW / TILE, HW / TILE, 24);   // 8 x 8 x (B*C)
    bilateral_kernel<<<grid, block>>>(x, out);
}

// round 7
// speedup vs baseline: 1.5741x; 1.0673x over previous
#include <cuda_runtime.h>

// Bilateral filter: B=8, C=3, H=W=512, K=5, sigma_s=2.0, sigma_r=0.1
//
// R7: same pairwise-shared-exp algorithm as R5/R6 (4x4 patch/thread,
// 294 EX2 per 16 px, baked log2-spatial immediates, exactly-1.0 center).
// Changes aimed at issue efficiency:
//   - 128-thread CTAs (64x32 tile), launch_bounds(128,8): halves the work
//     quantum -> smaller end-of-launch tail, better intra-SM staggering.
//   - 2-row register ring; di=2 partner row re-read from smem (12 extra
//     LDS.128, LDS pipe is idle) -> 8 fewer persistent regs under the hard
//     64-reg cap = more scheduler temps for EX2 pipelining.

#define HW   512
#define TILEW 64
#define TILEH 32
#define SROW 68
#define C1F  8.4932165750422091f
#define LSOF(dsq) (-0.18033688011112043f * (float)(dsq))   // log2(exp(-dsq/8))

__device__ __forceinline__ float ex2a(float v) {
    float y;
    asm("ex2.approx.ftz.f32 %0, %1;" : "=f"(y) : "f"(v));
    return y;
}

__device__ __forceinline__ int reflect512(int g) {
    g = (g < 0) ? -g : g;
    return (g > 511) ? (1022 - g) : g;
}

// ownership of a window-local coordinate (window is 8x8, owned core is 2..5)
#define OWN(rr,cc) ((rr) >= 2 && (rr) <= 5 && (cc) >= 2 && (cc) <= 5)

// one unordered pair; all index args compile-time constants after unrolling
#define PAIR(va, vb, ra, ca, rb, cb, di, dj) do {                              \
    const bool oa_ = OWN(ra, ca), ob_ = OWN(rb, cb);                           \
    if (oa_ || ob_) {                                                          \
        float t_ = (va) - (vb);                                                \
        float w_ = ex2a(fmaf(t_, -t_, LSOF((di)*(di)+(dj)*(dj))));             \
        if (oa_) { const int ia_ = ((ra)-2)*4 + ((ca)-2);                      \
                   wsum[ia_] += w_; acc[ia_] = fmaf(w_, (vb), acc[ia_]); }     \
        if (ob_) { const int ib_ = ((rb)-2)*4 + ((cb)-2);                      \
                   wsum[ib_] += w_; acc[ib_] = fmaf(w_, (va), acc[ib_]); }     \
    }                                                                          \
} while (0)

__global__ __launch_bounds__(128, 8)
void bilateral_kernel(const float* __restrict__ x,
                      float* __restrict__ out) {
    __shared__ float tile[36 * SROW];

    const int bx = blockIdx.x * TILEW;
    const int by = blockIdx.y * TILEH;
    const float* __restrict__ src = x   + (size_t)blockIdx.z * (HW * HW);
    float* __restrict__       dst = out + (size_t)blockIdx.z * (HW * HW);

    const int tx  = threadIdx.x;         // 0..15
    const int ty  = threadIdx.y;         // 0..7
    const int tid = ty * 16 + tx;

    const bool interior = (bx != 0) && (bx != HW - TILEW) &&
                          (by != 0) && (by != HW - TILEH);

    if (interior) {
        const float* base = src + (size_t)(by - 2) * HW + (bx - 2);
        const int c6 = tid & 63;
        const int r2 = tid >> 6;          // 0..1
        // main region: 36 rows x cols 0..63 (18 passes of 2 rows)
        #pragma unroll
        for (int it = 0; it < 18; it++) {
            const int r = it * 2 + r2;
            tile[r * SROW + c6] = base[r * HW + c6] * C1F;
        }
        // strip: cols 64..67, 36 rows (144 elems, 2 guarded passes)
        #pragma unroll
        for (int it = 0; it < 2; it++) {
            const int idx = it * 128 + tid;
            if (idx < 144) {
                const int r = idx >> 2;
                const int c = 64 + (idx & 3);
                tile[r * SROW + c] = base[r * HW + c] * C1F;
            }
        }
    } else {
        for (int i = tid; i < 36 * 68; i += 128) {
            const int r = i / 68;
            const int c = i - r * 68;
            tile[r * SROW + c] = src[reflect512(by + r - 2) * HW +
                                     reflect512(bx + c - 2)] * C1F;
        }
    }
    __syncthreads();

    const int R0 = 4 * ty;   // smem row of window origin (0..28)
    const int C0 = 4 * tx;   // smem col of window origin (0..60)

    float wsum[16], acc[16];
    #pragma unroll
    for (int i = 0; i < 16; i++) { wsum[i] = 0.0f; acc[i] = 0.0f; }

    float rows[2][8];   // 2-row ping-pong ring (constant indices after unroll)

    #pragma unroll
    for (int r = 0; r < 8; r++) {
        const int cr = r & 1;

        // load window row r: cols C0..C0+7, two aligned float4 (conflict-free)
        {
            float4 a = *(const float4*)&tile[(R0 + r) * SROW + C0];
            float4 b = *(const float4*)&tile[(R0 + r) * SROW + C0 + 4];
            rows[cr][0] = a.x; rows[cr][1] = a.y;
            rows[cr][2] = a.z; rows[cr][3] = a.w;
            rows[cr][4] = b.x; rows[cr][5] = b.y;
            rows[cr][6] = b.z; rows[cr][7] = b.w;
        }

        // ---- center taps: weight is exactly 1.0, no exp
        if (r >= 2 && r <= 5) {
            #pragma unroll
            for (int c = 2; c <= 5; c++) {
                const int ia = (r - 2) * 4 + (c - 2);
                wsum[ia] += 1.0f;
                acc[ia]  += rows[cr][c];
            }
        }

        // ---- di=0 pairs (within row r)
        if (r >= 2 && r <= 5) {
            #pragma unroll
            for (int c = 1; c <= 5; c++)       // dj = 1
                PAIR(rows[cr][c], rows[cr][c+1], r, c, r, c+1, 0, 1);
            #pragma unroll
            for (int c = 0; c <= 5; c++)       // dj = 2
                PAIR(rows[cr][c], rows[cr][c+2], r, c, r, c+2, 0, 2);
        }

        // ---- di=1 pairs: rows (r-1, r) from the ring
        if (r >= 1) {
            const int pr = (r - 1) & 1;
            #pragma unroll
            for (int dj = -2; dj <= 2; dj++) {
                #pragma unroll
                for (int c = 0; c < 8; c++) {
                    const int cb = c + dj;
                    if (cb < 0 || cb > 7) continue;
                    PAIR(rows[pr][c], rows[cr][cb], r-1, c, r, cb, 1, dj);
                }
            }
        }

        // ---- di=2 pairs: partner row r-2 re-read from smem (transient regs)
        if (r >= 2) {
            float p2[8];
            {
                float4 a = *(const float4*)&tile[(R0 + r - 2) * SROW + C0];
                float4 b = *(const float4*)&tile[(R0 + r - 2) * SROW + C0 + 4];
                p2[0] = a.x; p2[1] = a.y; p2[2] = a.z; p2[3] = a.w;
                p2[4] = b.x; p2[5] = b.y; p2[6] = b.z; p2[7] = b.w;
            }
            #pragma unroll
            for (int dj = -2; dj <= 2; dj++) {
                #pragma unroll
                for (int c = 0; c < 8; c++) {
                    const int cb = c + dj;
                    if (cb < 0 || cb > 7) continue;
                    PAIR(p2[c], rows[cr][cb], r-2, c, r, cb, 2, dj);
                }
            }
        }
    }

    // ---- normalize, un-scale by 1/C1, store
    const float INV = 1.0f / C1F;
    #pragma unroll
    for (int pr = 0; pr < 4; pr++) {
        float4 o;
        o.x = __fdividef(acc[pr*4 + 0], wsum[pr*4 + 0]) * INV;
        o.y = __fdividef(acc[pr*4 + 1], wsum[pr*4 + 1]) * INV;
        o.z = __fdividef(acc[pr*4 + 2], wsum[pr*4 + 2]) * INV;
        o.w = __fdividef(acc[pr*4 + 3], wsum[pr*4 + 3]) * INV;
        *(float4*)&dst[(by + R0 + pr) * HW + bx + C0] = o;
    }
}

extern "C" void kernel_launch(void* const* d_in, const int* in_sizes, int n_in,
                              void* d_out, int out_size) {
    const float* x = (const float*)d_in[0];  // (8,3,512,512)
    float* out     = (float*)d_out;

    dim3 block(16, 8);
    dim3 grid(HW / TILEW, HW / TILEH, 24);   // 8 x 16 x 24 = 3072 CTAs
    bilateral_kernel<<<grid, block>>>(x, out);
}